// round 3
// baseline (speedup 1.0000x reference)
#include <cuda_runtime.h>

#define N_NODES 100000
#define N_EDGES 1600000
#define DF 128
#define HF 32
#define NL 4

// ---------------- device scratch (no allocation allowed) ----------------
__device__ float g_P [N_NODES * HF];   // X @ W1^T
__device__ float g_SP[N_NODES * HF];   // (1+eps)P + b1 + segsum(P[src])  == Y1
__device__ float g_Y2[N_NODES * HF];
__device__ float g_X [N_NODES * DF];   // inter-layer features
__device__ float g_sum[HF];
__device__ float g_sq [HF];
__device__ float g_a  [HF];            // BN scale
__device__ float g_c  [HF];            // BN shift
__device__ int   g_idx64;

// ---------------- index dtype detection (int64 vs int32) ----------------
__global__ void detect_kernel(const int* __restrict__ idx)
{
    // If edge_index is int64 (little-endian, values < 2^31), every odd 32-bit
    // word of the first entries is 0. If int32, odd words are random dst/src
    // values in [0, 100000): P(2048 of them all zero) ~ 0.
    int flag = 1;
    for (int i = 0; i < 2048; i++) {
        if (idx[2 * i + 1] != 0) { flag = 0; break; }
    }
    g_idx64 = flag;
}

// ---------------- GEMM1: P = X @ W1^T ; SP = (1+eps)*P + b1 ----------------
// X:[N,128], W:[32,128] row-major. Tile 64 nodes x 32 cols, K chunked by 64.
__global__ __launch_bounds__(128) void gemm1_kernel(
    const float* __restrict__ X, const float* __restrict__ W,
    const float* __restrict__ b, const float* __restrict__ eps_arr, int layer,
    float* __restrict__ P, float* __restrict__ SP)
{
    __shared__ float Xs[64 * 65];   // [k(0..63)][node] stride 65
    __shared__ float Ws[128 * 33];  // [k][col]        stride 33

    const int tid = threadIdx.x;
    const int node0 = blockIdx.x * 64;
    const int cg = tid & 7;    // cols 4*cg .. 4*cg+3
    const int ng = tid >> 3;   // nodes 4*ng .. 4*ng+3 (0..15)

    // load W (32x128) -> Ws[k][c]
    for (int i = tid; i < 32 * 128; i += 128) {
        int c = i >> 7, k = i & 127;
        Ws[k * 33 + c] = W[i];
    }

    float acc[4][4] = {};

    for (int kk = 0; kk < 128; kk += 64) {
        __syncthreads();
        // load 64 nodes x 64 k-values (coalesced float4 along k)
        for (int i = tid; i < 64 * 16; i += 128) {
            int node = i >> 4;
            int k4   = i & 15;
            int gnode = node0 + node;
            float4 v = make_float4(0.f, 0.f, 0.f, 0.f);
            if (gnode < N_NODES)
                v = ((const float4*)(X + (long)gnode * DF + kk))[k4];
            int kb = k4 * 4;
            Xs[(kb + 0) * 65 + node] = v.x;
            Xs[(kb + 1) * 65 + node] = v.y;
            Xs[(kb + 2) * 65 + node] = v.z;
            Xs[(kb + 3) * 65 + node] = v.w;
        }
        __syncthreads();

#pragma unroll 4
        for (int k = 0; k < 64; k++) {
            const int gk = kk + k;
            float a0 = Xs[k * 65 + 4 * ng + 0];
            float a1 = Xs[k * 65 + 4 * ng + 1];
            float a2 = Xs[k * 65 + 4 * ng + 2];
            float a3 = Xs[k * 65 + 4 * ng + 3];
            float w0 = Ws[gk * 33 + 4 * cg + 0];
            float w1 = Ws[gk * 33 + 4 * cg + 1];
            float w2 = Ws[gk * 33 + 4 * cg + 2];
            float w3 = Ws[gk * 33 + 4 * cg + 3];
            acc[0][0] += a0 * w0; acc[0][1] += a0 * w1; acc[0][2] += a0 * w2; acc[0][3] += a0 * w3;
            acc[1][0] += a1 * w0; acc[1][1] += a1 * w1; acc[1][2] += a1 * w2; acc[1][3] += a1 * w3;
            acc[2][0] += a2 * w0; acc[2][1] += a2 * w1; acc[2][2] += a2 * w2; acc[2][3] += a2 * w3;
            acc[3][0] += a3 * w0; acc[3][1] += a3 * w1; acc[3][2] += a3 * w2; acc[3][3] += a3 * w3;
        }
    }

    const float ep = 1.0f + eps_arr[layer];
    const float b0 = b[4 * cg + 0], b1v = b[4 * cg + 1];
    const float b2v = b[4 * cg + 2], b3v = b[4 * cg + 3];
#pragma unroll
    for (int i = 0; i < 4; i++) {
        int gnode = node0 + 4 * ng + i;
        if (gnode < N_NODES) {
            float4 p = make_float4(acc[i][0], acc[i][1], acc[i][2], acc[i][3]);
            ((float4*)(P + (long)gnode * HF + 4 * cg))[0] = p;
            float4 sp = make_float4(ep * p.x + b0, ep * p.y + b1v,
                                    ep * p.z + b2v, ep * p.w + b3v);
            ((float4*)(SP + (long)gnode * HF + 4 * cg))[0] = sp;
        }
    }
}

// ---------------- scatter: SP[dst] += P[src], one warp handles 32 edges ----
__global__ __launch_bounds__(256) void scatter_kernel(
    const int* __restrict__ idx, const float* __restrict__ P,
    float* __restrict__ SP)
{
    const int lane = threadIdx.x & 31;
    const int warp = (blockIdx.x * blockDim.x + threadIdx.x) >> 5;
    const int e0 = warp * 32;          // N_EDGES % 32 == 0
    if (e0 >= N_EDGES) return;

    const int is64 = g_idx64;
    const int e = e0 + lane;
    int s, d;
    if (is64) { s = idx[2 * e]; d = idx[2 * (N_EDGES + e)]; }
    else      { s = idx[e];     d = idx[N_EDGES + e];       }

    for (int k = 0; k < 32; k++) {
        int ss = __shfl_sync(0xffffffffu, s, k);
        int dd = __shfl_sync(0xffffffffu, d, k);
        float v = P[(long)ss * HF + lane];
        atomicAdd(&SP[(long)dd * HF + lane], v);
    }
}

// ---------------- per-column sum / sum-of-squares over [N,32] -------------
__global__ __launch_bounds__(256) void zero_stats_kernel()
{
    if (threadIdx.x < HF) { g_sum[threadIdx.x] = 0.f; g_sq[threadIdx.x] = 0.f; }
}

__global__ __launch_bounds__(256) void stats_kernel(const float* __restrict__ Y)
{
    __shared__ float ssum[8][33];
    __shared__ float ssq [8][33];
    const int col = threadIdx.x & 31;
    const int row = threadIdx.x >> 5;   // 0..7
    float s = 0.f, q = 0.f;
    for (int n = blockIdx.x * 8 + row; n < N_NODES; n += gridDim.x * 8) {
        float v = Y[(long)n * HF + col];
        s += v; q += v * v;
    }
    ssum[row][col] = s;
    ssq [row][col] = q;
    __syncthreads();
    if (threadIdx.x < 32) {
        float ts = 0.f, tq = 0.f;
#pragma unroll
        for (int r = 0; r < 8; r++) { ts += ssum[r][threadIdx.x]; tq += ssq[r][threadIdx.x]; }
        atomicAdd(&g_sum[threadIdx.x], ts);
        atomicAdd(&g_sq [threadIdx.x], tq);
    }
}

__global__ __launch_bounds__(32) void coef_kernel(
    const float* __restrict__ gamma, const float* __restrict__ beta)
{
    int j = threadIdx.x;
    if (j < HF) {
        float m   = g_sum[j] * (1.0f / N_NODES);
        float var = g_sq[j] * (1.0f / N_NODES) - m * m;
        float inv = rsqrtf(var + 1e-5f);
        float a = gamma[j] * inv;
        g_a[j] = a;
        g_c[j] = beta[j] - m * a;
    }
}

// ---------------- GEMM2: Y2 = relu(a*Y1+c) @ W2^T + b2 --------------------
// Y1:[N,32], W2:[32,32]. Tile 64 nodes x 32 cols, K=32.
__global__ __launch_bounds__(128) void gemm2_kernel(
    const float* __restrict__ Y1, const float* __restrict__ W,
    const float* __restrict__ b, float* __restrict__ Y2)
{
    __shared__ float Xs[32 * 65];  // [k][node] stride 65
    __shared__ float Ws[32 * 33];  // [k][col]  stride 33

    const int tid = threadIdx.x;
    const int node0 = blockIdx.x * 64;
    const int cg = tid & 7;
    const int ng = tid >> 3;

    for (int i = tid; i < 32 * 32; i += 128) {
        int c = i >> 5, k = i & 31;
        Ws[k * 33 + c] = W[i];
    }
    // load 64 nodes x 32 k, with BN+ReLU applied
    for (int i = tid; i < 64 * 8; i += 128) {
        int node = i >> 3, k4 = i & 7;
        int gnode = node0 + node;
        float4 v = make_float4(0.f, 0.f, 0.f, 0.f);
        if (gnode < N_NODES)
            v = ((const float4*)(Y1 + (long)gnode * HF))[k4];
        int kb = 4 * k4;
        v.x = fmaxf(fmaf(g_a[kb + 0], v.x, g_c[kb + 0]), 0.f);
        v.y = fmaxf(fmaf(g_a[kb + 1], v.y, g_c[kb + 1]), 0.f);
        v.z = fmaxf(fmaf(g_a[kb + 2], v.z, g_c[kb + 2]), 0.f);
        v.w = fmaxf(fmaf(g_a[kb + 3], v.w, g_c[kb + 3]), 0.f);
        Xs[(kb + 0) * 65 + node] = v.x;
        Xs[(kb + 1) * 65 + node] = v.y;
        Xs[(kb + 2) * 65 + node] = v.z;
        Xs[(kb + 3) * 65 + node] = v.w;
    }
    __syncthreads();

    float acc[4][4] = {};
#pragma unroll 4
    for (int k = 0; k < 32; k++) {
        float a0 = Xs[k * 65 + 4 * ng + 0];
        float a1 = Xs[k * 65 + 4 * ng + 1];
        float a2 = Xs[k * 65 + 4 * ng + 2];
        float a3 = Xs[k * 65 + 4 * ng + 3];
        float w0 = Ws[k * 33 + 4 * cg + 0];
        float w1 = Ws[k * 33 + 4 * cg + 1];
        float w2 = Ws[k * 33 + 4 * cg + 2];
        float w3 = Ws[k * 33 + 4 * cg + 3];
        acc[0][0] += a0 * w0; acc[0][1] += a0 * w1; acc[0][2] += a0 * w2; acc[0][3] += a0 * w3;
        acc[1][0] += a1 * w0; acc[1][1] += a1 * w1; acc[1][2] += a1 * w2; acc[1][3] += a1 * w3;
        acc[2][0] += a2 * w0; acc[2][1] += a2 * w1; acc[2][2] += a2 * w2; acc[2][3] += a2 * w3;
        acc[3][0] += a3 * w0; acc[3][1] += a3 * w1; acc[3][2] += a3 * w2; acc[3][3] += a3 * w3;
    }

    const float b0 = b[4 * cg + 0], b1v = b[4 * cg + 1];
    const float b2v = b[4 * cg + 2], b3v = b[4 * cg + 3];
#pragma unroll
    for (int i = 0; i < 4; i++) {
        int gnode = node0 + 4 * ng + i;
        if (gnode < N_NODES) {
            float4 o = make_float4(acc[i][0] + b0, acc[i][1] + b1v,
                                   acc[i][2] + b2v, acc[i][3] + b3v);
            ((float4*)(Y2 + (long)gnode * HF + 4 * cg))[0] = o;
        }
    }
}

// ---------------- GEMM3: Xout = relu(a*Y2+c) @ W3^T + b3 ------------------
// Y2:[N,32], W3:[128,32]. Tile 64 nodes x 128 cols, K=32, 256 threads.
__global__ __launch_bounds__(256) void gemm3_kernel(
    const float* __restrict__ Y2, const float* __restrict__ W,
    const float* __restrict__ b, float* __restrict__ Xout)
{
    __shared__ float Xs[32 * 65];   // [k][node] stride 65
    __shared__ float Ws[32 * 129];  // [h][d]    stride 129

    const int tid = threadIdx.x;
    const int node0 = blockIdx.x * 64;
    const int cg = tid & 15;        // cols cg + 16*j, j=0..7
    const int ng = tid >> 4;        // nodes 4*ng .. 4*ng+3 (0..15)

    for (int i = tid; i < 128 * 32; i += 256) {
        int d = i >> 5, h = i & 31;
        Ws[h * 129 + d] = W[i];
    }
    for (int i = tid; i < 64 * 8; i += 256) {
        int node = i >> 3, k4 = i & 7;
        int gnode = node0 + node;
        float4 v = make_float4(0.f, 0.f, 0.f, 0.f);
        if (gnode < N_NODES)
            v = ((const float4*)(Y2 + (long)gnode * HF))[k4];
        int kb = 4 * k4;
        v.x = fmaxf(fmaf(g_a[kb + 0], v.x, g_c[kb + 0]), 0.f);
        v.y = fmaxf(fmaf(g_a[kb + 1], v.y, g_c[kb + 1]), 0.f);
        v.z = fmaxf(fmaf(g_a[kb + 2], v.z, g_c[kb + 2]), 0.f);
        v.w = fmaxf(fmaf(g_a[kb + 3], v.w, g_c[kb + 3]), 0.f);
        Xs[(kb + 0) * 65 + node] = v.x;
        Xs[(kb + 1) * 65 + node] = v.y;
        Xs[(kb + 2) * 65 + node] = v.z;
        Xs[(kb + 3) * 65 + node] = v.w;
    }
    __syncthreads();

    float acc[4][8] = {};
#pragma unroll 4
    for (int k = 0; k < 32; k++) {
        float a0 = Xs[k * 65 + 4 * ng + 0];
        float a1 = Xs[k * 65 + 4 * ng + 1];
        float a2 = Xs[k * 65 + 4 * ng + 2];
        float a3 = Xs[k * 65 + 4 * ng + 3];
        float bb[8];
#pragma unroll
        for (int j = 0; j < 8; j++) bb[j] = Ws[k * 129 + cg + 16 * j];
#pragma unroll
        for (int j = 0; j < 8; j++) {
            acc[0][j] += a0 * bb[j];
            acc[1][j] += a1 * bb[j];
            acc[2][j] += a2 * bb[j];
            acc[3][j] += a3 * bb[j];
        }
    }

#pragma unroll
    for (int i = 0; i < 4; i++) {
        int gnode = node0 + 4 * ng + i;
        if (gnode < N_NODES) {
            float* orow = Xout + (long)gnode * DF;
#pragma unroll
            for (int j = 0; j < 8; j++) {
                int col = cg + 16 * j;
                orow[col] = acc[i][j] + b[col];
            }
        }
    }
}

// --------------------------------- launch ---------------------------------
extern "C" void kernel_launch(void* const* d_in, const int* in_sizes, int n_in,
                              void* d_out, int out_size)
{
    (void)in_sizes; (void)n_in; (void)out_size;
    const float* X0  = (const float*)d_in[0];
    const int*   idx = (const int*)  d_in[1];   // int32 or int64 (auto-detected)
    const float* eps = (const float*)d_in[2];
    const float* W1  = (const float*)d_in[3];
    const float* b1  = (const float*)d_in[4];
    const float* g1  = (const float*)d_in[5];
    const float* bt1 = (const float*)d_in[6];
    const float* W2  = (const float*)d_in[7];
    const float* b2  = (const float*)d_in[8];
    const float* g2  = (const float*)d_in[9];
    const float* bt2 = (const float*)d_in[10];
    const float* W3  = (const float*)d_in[11];
    const float* b3  = (const float*)d_in[12];
    float* out = (float*)d_out;

    float *pP, *pSP, *pY2, *pX;
    cudaGetSymbolAddress((void**)&pP,  g_P);
    cudaGetSymbolAddress((void**)&pSP, g_SP);
    cudaGetSymbolAddress((void**)&pY2, g_Y2);
    cudaGetSymbolAddress((void**)&pX,  g_X);

    const int gemm_blocks = (N_NODES + 63) / 64;          // 1563
    const int scat_blocks = (N_EDGES / 32 + 7) / 8;       // 6250 (8 warps/block)

    detect_kernel<<<1, 1>>>(idx);

    for (int l = 0; l < NL; l++) {
        const float* Xc = (l == 0) ? X0 : pX;
        float* Xn = (l == NL - 1) ? out : pX;

        gemm1_kernel<<<gemm_blocks, 128>>>(Xc, W1 + l * HF * DF, b1 + l * HF,
                                           eps, l, pP, pSP);
        scatter_kernel<<<scat_blocks, 256>>>(idx, pP, pSP);

        zero_stats_kernel<<<1, 32>>>();
        stats_kernel<<<256, 256>>>(pSP);
        coef_kernel<<<1, 32>>>(g1 + l * HF, bt1 + l * HF);

        gemm2_kernel<<<gemm_blocks, 128>>>(pSP, W2 + l * HF * HF, b2 + l * HF, pY2);

        zero_stats_kernel<<<1, 32>>>();
        stats_kernel<<<256, 256>>>(pY2);
        coef_kernel<<<1, 32>>>(g2 + l * HF, bt2 + l * HF);

        gemm3_kernel<<<gemm_blocks, 256>>>(pY2, W3 + l * DF * HF, b3 + l * DF, Xn);
    }
}

// round 4
// speedup vs baseline: 1.0781x; 1.0781x over previous
#include <cuda_runtime.h>

#define N_NODES 100000
#define N_EDGES 1600000
#define DF 128
#define HF 32
#define NL 4

typedef unsigned long long u64;

// ---------------- device scratch (no allocation allowed) ----------------
__device__ float g_P [N_NODES * HF];   // X @ W1^T
__device__ float g_SP[N_NODES * HF];   // (1+eps)P + b1 + segsum(P[src]) == Y1
__device__ float g_Y2[N_NODES * HF];
__device__ float g_X [N_NODES * DF];   // inter-layer features
__device__ float g_sumA[HF], g_sqA[HF];   // stats accumulators for SP
__device__ float g_sumB[HF], g_sqB[HF];   // stats accumulators for Y2
__device__ unsigned g_cntA, g_cntB;
__device__ float g_a [HF], g_c [HF];      // BN coefs for SP  (used by gemm2)
__device__ float g_a2[HF], g_c2[HF];      // BN coefs for Y2 (used by gemm3)
__device__ int   g_idx64;

// ---------------- f32x2 helpers ----------------
__device__ __forceinline__ u64 pk2(float v) {
    u64 r; asm("mov.b64 %0,{%1,%1};" : "=l"(r) : "f"(v)); return r;
}
__device__ __forceinline__ void fma2(u64& d, u64 a, u64 b) {
    asm("fma.rn.f32x2 %0,%1,%2,%3;" : "=l"(d) : "l"(a), "l"(b), "l"(d));
}
__device__ __forceinline__ float2 up2(u64 v) {
    float2 r; asm("mov.b64 {%0,%1},%2;" : "=f"(r.x), "=f"(r.y) : "l"(v)); return r;
}

// ---------------- index dtype detection (int64 vs int32) ----------------
__global__ void detect_kernel(const int* __restrict__ idx)
{
    int flag = 1;
    for (int i = 0; i < 2048; i++) {
        if (idx[2 * i + 1] != 0) { flag = 0; break; }
    }
    g_idx64 = flag;
}

// ---------------- GEMM1: P = X @ W1^T ; SP = (1+eps)*P + b1 ----------------
// X:[N,128], W:[32,128]. Tile 64 nodes x 32 cols; f32x2 packed over col pairs.
__global__ __launch_bounds__(128) void gemm1_kernel(
    const float* __restrict__ X, const float* __restrict__ W,
    const float* __restrict__ b, const float* __restrict__ eps_arr, int layer,
    float* __restrict__ P, float* __restrict__ SP)
{
    __shared__ __align__(16) float Xs[64 * 68];   // [k(0..63)][node] stride 68
    __shared__ __align__(16) float Ws[128 * 36];  // [k][col]        stride 36

    const int tid = threadIdx.x;
    const int node0 = blockIdx.x * 64;
    const int cg = tid & 7;    // cols 4*cg .. 4*cg+3
    const int ng = tid >> 3;   // nodes 4*ng .. 4*ng+3

    for (int i = tid; i < 32 * 128; i += 128) {
        int c = i >> 7, k = i & 127;
        Ws[k * 36 + c] = W[i];
    }

    u64 acc[4][2] = {};   // [node][colpair], each u64 = (c, c+1)

    for (int kk = 0; kk < 128; kk += 64) {
        __syncthreads();
        for (int i = tid; i < 64 * 16; i += 128) {
            int node = i >> 4;
            int k4   = i & 15;
            int gnode = node0 + node;
            float4 v = make_float4(0.f, 0.f, 0.f, 0.f);
            if (gnode < N_NODES)
                v = ((const float4*)(X + (size_t)gnode * DF + kk))[k4];
            int kb = k4 * 4;
            Xs[(kb + 0) * 68 + node] = v.x;
            Xs[(kb + 1) * 68 + node] = v.y;
            Xs[(kb + 2) * 68 + node] = v.z;
            Xs[(kb + 3) * 68 + node] = v.w;
        }
        __syncthreads();

#pragma unroll 8
        for (int k = 0; k < 64; k++) {
            float4 av = *(const float4*)&Xs[k * 68 + 4 * ng];
            ulonglong2 wv = *(const ulonglong2*)&Ws[(kk + k) * 36 + 4 * cg];
            u64 a0 = pk2(av.x), a1 = pk2(av.y), a2 = pk2(av.z), a3 = pk2(av.w);
            fma2(acc[0][0], a0, wv.x); fma2(acc[0][1], a0, wv.y);
            fma2(acc[1][0], a1, wv.x); fma2(acc[1][1], a1, wv.y);
            fma2(acc[2][0], a2, wv.x); fma2(acc[2][1], a2, wv.y);
            fma2(acc[3][0], a3, wv.x); fma2(acc[3][1], a3, wv.y);
        }
    }

    const float ep = 1.0f + eps_arr[layer];
    const float b0 = b[4 * cg + 0], b1v = b[4 * cg + 1];
    const float b2v = b[4 * cg + 2], b3v = b[4 * cg + 3];
#pragma unroll
    for (int i = 0; i < 4; i++) {
        int gnode = node0 + 4 * ng + i;
        if (gnode < N_NODES) {
            float2 p01 = up2(acc[i][0]);
            float2 p23 = up2(acc[i][1]);
            float4 p = make_float4(p01.x, p01.y, p23.x, p23.y);
            ((float4*)(P + (size_t)gnode * HF + 4 * cg))[0] = p;
            float4 sp = make_float4(fmaf(ep, p.x, b0), fmaf(ep, p.y, b1v),
                                    fmaf(ep, p.z, b2v), fmaf(ep, p.w, b3v));
            ((float4*)(SP + (size_t)gnode * HF + 4 * cg))[0] = sp;
        }
    }
}

// ---------------- scatter: SP[dst] += P[src], vectored red.v4 -------------
// One warp per 32 edges; 8 lanes per edge row, float4 each, 4 edges/iter.
__global__ __launch_bounds__(256) void scatter_kernel(
    const int* __restrict__ idx, const float* __restrict__ P,
    float* __restrict__ SP)
{
    const int lane = threadIdx.x & 31;
    const int warp = (blockIdx.x * blockDim.x + threadIdx.x) >> 5;
    const int e0 = warp * 32;          // N_EDGES % 32 == 0
    if (e0 >= N_EDGES) return;

    const int e = e0 + lane;
    int s, d;
    if (g_idx64) { s = idx[2 * e]; d = idx[2 * (N_EDGES + e)]; }
    else         { s = idx[e];     d = idx[N_EDGES + e];       }

    const int sub = lane >> 3;   // which of 4 edges this iteration
    const int q   = lane & 7;    // float4 chunk within the 32-float row

#pragma unroll
    for (int k = 0; k < 8; k++) {
        int src_lane = k * 4 + sub;
        int ss = __shfl_sync(0xffffffffu, s, src_lane);
        int dd = __shfl_sync(0xffffffffu, d, src_lane);
        float4 v = *(const float4*)&P[(size_t)ss * HF + 4 * q];
        asm volatile("red.global.add.v4.f32 [%0], {%1,%2,%3,%4};"
                     :: "l"(&SP[(size_t)dd * HF + 4 * q]),
                        "f"(v.x), "f"(v.y), "f"(v.z), "f"(v.w)
                     : "memory");
    }
}

// ------------- fused stats+coef over SP (BN1), last block computes --------
__global__ __launch_bounds__(256) void statsA_kernel(
    const float* __restrict__ Y, const float* __restrict__ gamma,
    const float* __restrict__ beta)
{
    __shared__ float ssum[8][33];
    __shared__ float ssq [8][33];
    __shared__ bool  is_last;
    const int col = threadIdx.x & 31;
    const int row = threadIdx.x >> 5;
    float s = 0.f, q = 0.f;
    for (int n = blockIdx.x * 8 + row; n < N_NODES; n += gridDim.x * 8) {
        float v = Y[(size_t)n * HF + col];
        s += v; q += v * v;
    }
    ssum[row][col] = s;
    ssq [row][col] = q;
    __syncthreads();
    if (threadIdx.x < 32) {
        float ts = 0.f, tq = 0.f;
#pragma unroll
        for (int r = 0; r < 8; r++) { ts += ssum[r][threadIdx.x]; tq += ssq[r][threadIdx.x]; }
        atomicAdd(&g_sumA[threadIdx.x], ts);
        atomicAdd(&g_sqA [threadIdx.x], tq);
    }
    __threadfence();
    __syncthreads();
    if (threadIdx.x == 0) {
        unsigned t = atomicAdd(&g_cntA, 1u);
        is_last = (t == (unsigned)gridDim.x - 1u);
    }
    __syncthreads();
    if (is_last && threadIdx.x < 32) {
        int j = threadIdx.x;
        float m   = g_sumA[j] * (1.0f / N_NODES);
        float var = g_sqA[j] * (1.0f / N_NODES) - m * m;
        float inv = rsqrtf(var + 1e-5f);
        float a = gamma[j] * inv;
        g_a[j] = a;
        g_c[j] = beta[j] - m * a;
        g_sumA[j] = 0.f; g_sqA[j] = 0.f;
        if (j == 0) g_cntA = 0u;
    }
}

// ---------------- GEMM2: Y2 = relu(a*Y1+c) @ W2^T + b2 --------------------
// Fused Y2 batch stats + coef2 (last block) in the epilogue.
__global__ __launch_bounds__(128) void gemm2_kernel(
    const float* __restrict__ Y1, const float* __restrict__ W,
    const float* __restrict__ b, const float* __restrict__ gamma,
    const float* __restrict__ beta, float* __restrict__ Y2)
{
    __shared__ __align__(16) float Xs[32 * 68];
    __shared__ __align__(16) float Ws[32 * 36];
    __shared__ float rsum[16][33];
    __shared__ float rsq [16][33];
    __shared__ bool  is_last;

    const int tid = threadIdx.x;
    const int node0 = blockIdx.x * 64;
    const int cg = tid & 7;
    const int ng = tid >> 3;

    for (int i = tid; i < 32 * 32; i += 128) {
        int c = i >> 5, k = i & 31;
        Ws[k * 36 + c] = W[i];
    }
    for (int i = tid; i < 64 * 8; i += 128) {
        int node = i >> 3, k4 = i & 7;
        int gnode = node0 + node;
        float4 v = make_float4(0.f, 0.f, 0.f, 0.f);
        if (gnode < N_NODES)
            v = ((const float4*)(Y1 + (size_t)gnode * HF))[k4];
        int kb = 4 * k4;
        v.x = fmaxf(fmaf(g_a[kb + 0], v.x, g_c[kb + 0]), 0.f);
        v.y = fmaxf(fmaf(g_a[kb + 1], v.y, g_c[kb + 1]), 0.f);
        v.z = fmaxf(fmaf(g_a[kb + 2], v.z, g_c[kb + 2]), 0.f);
        v.w = fmaxf(fmaf(g_a[kb + 3], v.w, g_c[kb + 3]), 0.f);
        Xs[(kb + 0) * 68 + node] = v.x;
        Xs[(kb + 1) * 68 + node] = v.y;
        Xs[(kb + 2) * 68 + node] = v.z;
        Xs[(kb + 3) * 68 + node] = v.w;
    }
    __syncthreads();

    u64 acc[4][2] = {};
#pragma unroll 8
    for (int k = 0; k < 32; k++) {
        float4 av = *(const float4*)&Xs[k * 68 + 4 * ng];
        ulonglong2 wv = *(const ulonglong2*)&Ws[k * 36 + 4 * cg];
        u64 a0 = pk2(av.x), a1 = pk2(av.y), a2 = pk2(av.z), a3 = pk2(av.w);
        fma2(acc[0][0], a0, wv.x); fma2(acc[0][1], a0, wv.y);
        fma2(acc[1][0], a1, wv.x); fma2(acc[1][1], a1, wv.y);
        fma2(acc[2][0], a2, wv.x); fma2(acc[2][1], a2, wv.y);
        fma2(acc[3][0], a3, wv.x); fma2(acc[3][1], a3, wv.y);
    }

    const float b0 = b[4 * cg + 0], b1v = b[4 * cg + 1];
    const float b2v = b[4 * cg + 2], b3v = b[4 * cg + 3];
    float cs[4] = {0.f, 0.f, 0.f, 0.f};
    float cq[4] = {0.f, 0.f, 0.f, 0.f};
#pragma unroll
    for (int i = 0; i < 4; i++) {
        int gnode = node0 + 4 * ng + i;
        float2 p01 = up2(acc[i][0]);
        float2 p23 = up2(acc[i][1]);
        float4 o = make_float4(p01.x + b0, p01.y + b1v, p23.x + b2v, p23.y + b3v);
        if (gnode < N_NODES) {
            ((float4*)(Y2 + (size_t)gnode * HF + 4 * cg))[0] = o;
            cs[0] += o.x; cs[1] += o.y; cs[2] += o.z; cs[3] += o.w;
            cq[0] += o.x * o.x; cq[1] += o.y * o.y;
            cq[2] += o.z * o.z; cq[3] += o.w * o.w;
        }
    }
#pragma unroll
    for (int j = 0; j < 4; j++) { rsum[ng][4 * cg + j] = cs[j]; rsq[ng][4 * cg + j] = cq[j]; }
    __syncthreads();
    if (tid < 32) {
        float ts = 0.f, tq = 0.f;
#pragma unroll
        for (int r = 0; r < 16; r++) { ts += rsum[r][tid]; tq += rsq[r][tid]; }
        atomicAdd(&g_sumB[tid], ts);
        atomicAdd(&g_sqB [tid], tq);
    }
    __threadfence();
    __syncthreads();
    if (tid == 0) {
        unsigned t = atomicAdd(&g_cntB, 1u);
        is_last = (t == (unsigned)gridDim.x - 1u);
    }
    __syncthreads();
    if (is_last && tid < 32) {
        int j = tid;
        float m   = g_sumB[j] * (1.0f / N_NODES);
        float var = g_sqB[j] * (1.0f / N_NODES) - m * m;
        float inv = rsqrtf(var + 1e-5f);
        float a = gamma[j] * inv;
        g_a2[j] = a;
        g_c2[j] = beta[j] - m * a;
        g_sumB[j] = 0.f; g_sqB[j] = 0.f;
        if (j == 0) g_cntB = 0u;
    }
}

// ---------------- GEMM3: Xout = relu(a2*Y2+c2) @ W3^T + b3 ----------------
// Tile 64 nodes x 128 cols, 256 threads; f32x2 packed over col pairs.
__global__ __launch_bounds__(256) void gemm3_kernel(
    const float* __restrict__ Y2, const float* __restrict__ W,
    const float* __restrict__ b, float* __restrict__ Xout)
{
    __shared__ __align__(16) float Xs[32 * 68];    // [k][node] stride 68
    __shared__ __align__(16) float Ws[32 * 132];   // [h][d]    stride 132

    const int tid = threadIdx.x;
    const int node0 = blockIdx.x * 64;
    const int cg = tid & 31;        // cols 4*cg .. 4*cg+3
    const int ng = tid >> 5;        // nodes 8*ng .. 8*ng+7

    for (int i = tid; i < 128 * 32; i += 256) {
        int d = i >> 5, h = i & 31;
        Ws[h * 132 + d] = W[i];
    }
    for (int i = tid; i < 64 * 8; i += 256) {
        int node = i >> 3, k4 = i & 7;
        int gnode = node0 + node;
        float4 v = make_float4(0.f, 0.f, 0.f, 0.f);
        if (gnode < N_NODES)
            v = ((const float4*)(Y2 + (size_t)gnode * HF))[k4];
        int kb = 4 * k4;
        v.x = fmaxf(fmaf(g_a2[kb + 0], v.x, g_c2[kb + 0]), 0.f);
        v.y = fmaxf(fmaf(g_a2[kb + 1], v.y, g_c2[kb + 1]), 0.f);
        v.z = fmaxf(fmaf(g_a2[kb + 2], v.z, g_c2[kb + 2]), 0.f);
        v.w = fmaxf(fmaf(g_a2[kb + 3], v.w, g_c2[kb + 3]), 0.f);
        Xs[(kb + 0) * 68 + node] = v.x;
        Xs[(kb + 1) * 68 + node] = v.y;
        Xs[(kb + 2) * 68 + node] = v.z;
        Xs[(kb + 3) * 68 + node] = v.w;
    }
    __syncthreads();

    u64 acc[8][2] = {};   // [node][colpair]
#pragma unroll 8
    for (int k = 0; k < 32; k++) {
        float4 av0 = *(const float4*)&Xs[k * 68 + 8 * ng];
        float4 av1 = *(const float4*)&Xs[k * 68 + 8 * ng + 4];
        ulonglong2 wv = *(const ulonglong2*)&Ws[k * 132 + 4 * cg];
        u64 a0 = pk2(av0.x), a1 = pk2(av0.y), a2 = pk2(av0.z), a3 = pk2(av0.w);
        u64 a4 = pk2(av1.x), a5 = pk2(av1.y), a6 = pk2(av1.z), a7 = pk2(av1.w);
        fma2(acc[0][0], a0, wv.x); fma2(acc[0][1], a0, wv.y);
        fma2(acc[1][0], a1, wv.x); fma2(acc[1][1], a1, wv.y);
        fma2(acc[2][0], a2, wv.x); fma2(acc[2][1], a2, wv.y);
        fma2(acc[3][0], a3, wv.x); fma2(acc[3][1], a3, wv.y);
        fma2(acc[4][0], a4, wv.x); fma2(acc[4][1], a4, wv.y);
        fma2(acc[5][0], a5, wv.x); fma2(acc[5][1], a5, wv.y);
        fma2(acc[6][0], a6, wv.x); fma2(acc[6][1], a6, wv.y);
        fma2(acc[7][0], a7, wv.x); fma2(acc[7][1], a7, wv.y);
    }

    const float b0 = b[4 * cg + 0], b1v = b[4 * cg + 1];
    const float b2v = b[4 * cg + 2], b3v = b[4 * cg + 3];
#pragma unroll
    for (int i = 0; i < 8; i++) {
        int gnode = node0 + 8 * ng + i;
        if (gnode < N_NODES) {
            float2 p01 = up2(acc[i][0]);
            float2 p23 = up2(acc[i][1]);
            float4 o = make_float4(p01.x + b0, p01.y + b1v, p23.x + b2v, p23.y + b3v);
            ((float4*)(Xout + (size_t)gnode * DF + 4 * cg))[0] = o;
        }
    }
}

// --------------------------------- launch ---------------------------------
extern "C" void kernel_launch(void* const* d_in, const int* in_sizes, int n_in,
                              void* d_out, int out_size)
{
    (void)in_sizes; (void)n_in; (void)out_size;
    const float* X0  = (const float*)d_in[0];
    const int*   idx = (const int*)  d_in[1];
    const float* eps = (const float*)d_in[2];
    const float* W1  = (const float*)d_in[3];
    const float* b1  = (const float*)d_in[4];
    const float* g1  = (const float*)d_in[5];
    const float* bt1 = (const float*)d_in[6];
    const float* W2  = (const float*)d_in[7];
    const float* b2  = (const float*)d_in[8];
    const float* g2  = (const float*)d_in[9];
    const float* bt2 = (const float*)d_in[10];
    const float* W3  = (const float*)d_in[11];
    const float* b3  = (const float*)d_in[12];
    float* out = (float*)d_out;

    float *pP, *pSP, *pY2, *pX;
    cudaGetSymbolAddress((void**)&pP,  g_P);
    cudaGetSymbolAddress((void**)&pSP, g_SP);
    cudaGetSymbolAddress((void**)&pY2, g_Y2);
    cudaGetSymbolAddress((void**)&pX,  g_X);

    const int gemm_blocks = (N_NODES + 63) / 64;      // 1563
    const int scat_blocks = (N_EDGES / 32 + 7) / 8;   // 6250

    detect_kernel<<<1, 1>>>(idx);

    for (int l = 0; l < NL; l++) {
        const float* Xc = (l == 0) ? X0 : pX;
        float* Xn = (l == NL - 1) ? out : pX;

        gemm1_kernel<<<gemm_blocks, 128>>>(Xc, W1 + l * HF * DF, b1 + l * HF,
                                           eps, l, pP, pSP);
        scatter_kernel<<<scat_blocks, 256>>>(idx, pP, pSP);
        statsA_kernel<<<240, 256>>>(pSP, g1 + l * HF, bt1 + l * HF);
        gemm2_kernel<<<gemm_blocks, 128>>>(pSP, W2 + l * HF * HF, b2 + l * HF,
                                           g2 + l * HF, bt2 + l * HF, pY2);
        gemm3_kernel<<<gemm_blocks, 256>>>(pY2, W3 + l * DF * HF, b3 + l * DF, Xn);
    }
}